// round 13
// baseline (speedup 1.0000x reference)
#include <cuda_runtime.h>
#include <cstdint>

#define IN_C  64
#define OUT_C 64
#define HH    112
#define WW    112
#define NB    2

#define TROWS 4
#define TCOLS 16
#define KTOT  576
#define NTAP  9

// raw planes: [window 108][ic 64] int8, row stride 80 B
#define RAW_WIN 108
#define RAW_STRIDE 80

// B tiles: per tap 64 rows x 144 B stride (128 int8 payload)
#define TSTRIDE 144u
#define BTAP (64u * TSTRIDE)        // 9216 B per tap

// smem offsets (main kernel)
#define OFF_B0   0u
#define OFF_B1   9216u
#define OFF_RAW1 18432u
#define OFF_RAW2 27072u
#define OFF_BIAS 35712u
#define SMEM_BYTES 35968u

// quantization scales
#define SX1 24.0f
#define SX2 6144.0f
#define SW1 512.0f
#define SW2 131072.0f
#define C1F (1.0f/12288.0f)
#define C2F (1.0f/3145728.0f)

__device__ __align__(16) int8_t BC_g[NTAP * 64 * TSTRIDE];
__device__ __align__(16) int8_t xq1_g[NB * HH * WW * IN_C];
__device__ __align__(16) int8_t xq2_g[NB * HH * WW * IN_C];

__device__ __forceinline__ uint32_t smem_u32(const void* p) {
    uint32_t a;
    asm("{ .reg .u64 t; cvta.to.shared.u64 t, %1; cvt.u32.u64 %0, t; }" : "=r"(a) : "l"(p));
    return a;
}
__device__ __forceinline__ void mma_s8(int* d, const uint32_t* a, const uint32_t* b) {
    asm volatile(
        "mma.sync.aligned.m16n8k32.row.col.s32.s8.s8.s32 "
        "{%0,%1,%2,%3}, {%4,%5,%6,%7}, {%8,%9}, {%0,%1,%2,%3};"
        : "+r"(d[0]), "+r"(d[1]), "+r"(d[2]), "+r"(d[3])
        : "r"(a[0]), "r"(a[1]), "r"(a[2]), "r"(a[3]), "r"(b[0]), "r"(b[1]));
}
__device__ __forceinline__ void ldmx4(uint32_t* r, uint32_t addr) {
    asm volatile("ldmatrix.sync.aligned.m8n8.x4.shared.b16 {%0,%1,%2,%3}, [%4];"
        : "=r"(r[0]), "=r"(r[1]), "=r"(r[2]), "=r"(r[3]) : "r"(addr));
}
__device__ __forceinline__ int clampi(int v) { return max(-127, min(127, v)); }

// ---- fused pre-kernel: grid (112, 2, 2) x 256 threads ----
// z selects ic-half (8 ic-groups); weight prep rides on z==0, flat<144
__global__ void __launch_bounds__(256)
prep_fused_kernel(const float* __restrict__ x, const float* __restrict__ wgt)
{
    __shared__ uint32_t s1w[WW * 9];
    __shared__ uint32_t s2w[WW * 9];

    const int tid = threadIdx.x;
    const int y   = blockIdx.x;
    const int b   = blockIdx.y;
    const int h   = blockIdx.z;         // ic half
    const int flat = b * HH + y;

    // ---- weight prep: 144 blocks x 256 = 36864 exact ----
    if (h == 0 && flat < 144) {
        const int i   = flat * 256 + tid;
        const int tap = i >> 12;
        const int n   = (i >> 6) & 63;
        const int ic  = i & 63;
        const float w = wgt[n * KTOT + ic * 9 + tap];
        int w1 = clampi(__float2int_rn(w * SW1));
        const float rw = w - (float)w1 * (1.0f / SW1);
        int w2 = clampi(__float2int_rn(rw * SW2));
        int8_t* row = BC_g + (tap * 64 + n) * TSTRIDE;
        row[ic]      = (int8_t)w2;
        row[64 + ic] = (int8_t)w1;
    }

    // ---- x quantize: 8 ic-groups x 112 x-positions ----
    for (int i = tid; i < 8 * WW; i += 256) {
        const int icl = i / WW;             // 0..7
        const int xx  = i - icl * WW;
        const int icg = h * 8 + icl;
        uint32_t p1 = 0, p2 = 0;
        #pragma unroll
        for (int j = 0; j < 4; ++j) {
            const float v = x[((b * IN_C + icg * 4 + j) * HH + y) * WW + xx];
            int x1 = clampi(__float2int_rn(v * SX1));
            const float rx = v - (float)x1 * (1.0f / SX1);
            int x2 = clampi(__float2int_rn(rx * SX2));
            p1 |= (uint32_t)(uint8_t)(int8_t)x1 << (j * 8);
            p2 |= (uint32_t)(uint8_t)(int8_t)x2 << (j * 8);
        }
        s1w[xx * 9 + icl] = p1;
        s2w[xx * 9 + icl] = p2;
    }
    __syncthreads();

    // ---- write out: per plane 112 xx x 2 local q-groups ----
    const int rowbase = ((b * HH + y) * WW) * IN_C;
    for (int i = tid; i < 448; i += 256) {
        const int pl = i >= 224;
        const int ii = pl ? i - 224 : i;
        const int xx = ii >> 1;
        const int ql = ii & 1;
        const int w0 = xx * 9 + ql * 4;
        const uint32_t* s = pl ? s2w : s1w;
        uint4 v = make_uint4(s[w0], s[w0 + 1], s[w0 + 2], s[w0 + 3]);
        int8_t* dst = pl ? xq2_g : xq1_g;
        *(uint4*)&dst[rowbase + xx * IN_C + (h * 2 + ql) * 16] = v;
    }
}

// ---- main kernel: 256 threads, 8 warps of 16m x 32n ----
__global__ void __launch_bounds__(256, 2)
conv3x3_i8_kernel(const float* __restrict__ bias,
                  float* __restrict__ out)
{
    extern __shared__ char sm[];
    const uint32_t sb = smem_u32(sm);

    const int tid  = threadIdx.x;
    const int wid  = tid >> 5;
    const int lane = tid & 31;
    const int grp  = lane >> 2;
    const int tid4 = lane & 3;

    const int wm = wid & 3;         // 4 m-groups of 16
    const int wn = wid >> 2;        // 2 n-groups of 32

    const int col0 = blockIdx.x * TCOLS;
    const int row0 = blockIdx.y * TROWS;
    const int b    = blockIdx.z;

    float* biass = (float*)(sm + OFF_BIAS);

    // ---- B prefetch (registers): 576 uint4 over 256 threads ----
    uint4 bpf[3];
    auto ldB = [&](int tap) {
        const uint4* g = (const uint4*)(BC_g + tap * BTAP);
        bpf[0] = g[tid];
        bpf[1] = g[tid + 256];
        if (tid < 64) bpf[2] = g[512 + tid];
    };
    auto stB = [&](uint32_t off) {
        uint4* s = (uint4*)(sm + off);
        s[tid]       = bpf[0];
        s[tid + 256] = bpf[1];
        if (tid < 64) s[512 + tid] = bpf[2];
    };

    ldB(0);

    // ---- stage raw planes: 16B copies from pre-quantized NHWC globals ----
    for (int e = tid; e < 432; e += 256) {
        const int wdw = e >> 2;
        const int icg = e & 3;
        const int r   = wdw / 18;
        const int c   = wdw - r * 18;
        const int gr  = row0 - 1 + r;
        const int gc  = col0 - 1 + c;
        uint4 v1 = make_uint4(0, 0, 0, 0), v2 = v1;
        if ((unsigned)gr < (unsigned)HH && (unsigned)gc < (unsigned)WW) {
            const int gi = (((b * HH + gr) * WW) + gc) * IN_C + icg * 16;
            v1 = *(const uint4*)&xq1_g[gi];
            v2 = *(const uint4*)&xq2_g[gi];
        }
        const uint32_t so = (uint32_t)wdw * RAW_STRIDE + (uint32_t)icg * 16u;
        *(uint4*)(sm + OFF_RAW1 + so) = v1;
        *(uint4*)(sm + OFF_RAW2 + so) = v2;
    }
    if (tid < OUT_C) biass[tid] = bias[tid];

    stB(OFF_B0);

    // accumulators: [n-frag 4][4] x 2 passes
    int acc1[4][4], acc2[4][4];
    #pragma unroll
    for (int g = 0; g < 4; ++g)
        #pragma unroll
        for (int qq = 0; qq < 4; ++qq) { acc1[g][qq] = 0; acc2[g][qq] = 0; }

    // ---- per-lane ldmatrix base addresses ----
    const int q  = lane >> 3;
    const int rq = lane & 7;
    const int m0 = wm * 16 + ((q & 1) << 3) + rq;
    const uint32_t baseA = sb + (uint32_t)((m0 >> 4) * 18 + (m0 & 15)) * RAW_STRIDE
                              + (uint32_t)((q >> 1) << 4);
    const uint32_t baseB = sb
        + (uint32_t)(wn * 32 + ((q >> 1) << 3) + rq) * TSTRIDE
        + (uint32_t)((q & 1) << 4);

    __syncthreads();                // raw planes + B0 staged

    #pragma unroll 1
    for (int tap = 0; tap < NTAP; ++tap) {
        const int dy = tap / 3, dx = tap - dy * 3;
        const uint32_t aA  = baseA + (uint32_t)(dy * 18 + dx) * RAW_STRIDE;
        const uint32_t aBt = baseB + (uint32_t)(tap & 1) * BTAP;

        if (tap < NTAP - 1) ldB(tap + 1);

        uint32_t B2[8], B3[8];
        ldmx4(B2,     aBt + 2 * 32);
        ldmx4(B2 + 4, aBt + 16u * TSTRIDE + 2 * 32);
        ldmx4(B3,     aBt + 3 * 32);
        ldmx4(B3 + 4, aBt + 16u * TSTRIDE + 3 * 32);

        // ks = 2, 3: cross pass (A plane 2)
        #pragma unroll
        for (int ks = 2; ks < 4; ++ks) {
            uint32_t A0[4];
            ldmx4(A0, aA + OFF_RAW2 + (uint32_t)(ks & 1) * 32u);
            uint32_t* Bk = (ks == 2) ? B2 : B3;
            #pragma unroll
            for (int g = 0; g < 4; ++g)
                mma_s8(acc2[g], A0, Bk + 2 * g);
        }
        // ks = 0, 1: cross with fresh B[ks], main with retained B[ks+2]
        #pragma unroll
        for (int ks = 0; ks < 2; ++ks) {
            uint32_t A0[4], Bk[8];
            ldmx4(A0, aA + OFF_RAW1 + (uint32_t)ks * 32u);
            ldmx4(Bk,     aBt + ks * 32);
            ldmx4(Bk + 4, aBt + 16u * TSTRIDE + ks * 32);
            uint32_t* Bm = (ks == 0) ? B2 : B3;
            #pragma unroll
            for (int g = 0; g < 4; ++g) {
                mma_s8(acc2[g], A0, Bk + 2 * g);
                mma_s8(acc1[g], A0, Bm + 2 * g);
            }
        }

        if (tap < NTAP - 1) {
            stB(OFF_B0 + (uint32_t)((tap + 1) & 1) * BTAP);
            __syncthreads();
        }
    }

    // ---- epilogue: reconstruct fp32, add bias, store ----
    #pragma unroll
    for (int half = 0; half < 2; ++half) {
        const int m  = wm * 16 + half * 8 + grp;
        const int gy = row0 + (m >> 4);
        const int gx = col0 + (m & 15);
        float* op = &out[((b * OUT_C) * HH + gy) * WW + gx];
        #pragma unroll
        for (int g = 0; g < 4; ++g) {
            const int n = wn * 32 + g * 8 + tid4 * 2;
            const float v0 = (float)acc1[g][half * 2]     * C1F
                           + (float)acc2[g][half * 2]     * C2F + biass[n];
            const float v1 = (float)acc1[g][half * 2 + 1] * C1F
                           + (float)acc2[g][half * 2 + 1] * C2F + biass[n + 1];
            op[n * (HH * WW)]       = v0;
            op[(n + 1) * (HH * WW)] = v1;
        }
    }
}

extern "C" void kernel_launch(void* const* d_in, const int* in_sizes, int n_in,
                              void* d_out, int out_size)
{
    const float* x    = (const float*)d_in[0];
    const float* wgt  = (const float*)d_in[1];
    const float* bias = (const float*)d_in[2];
    float* out        = (float*)d_out;

    cudaFuncSetAttribute(conv3x3_i8_kernel,
                         cudaFuncAttributeMaxDynamicSharedMemorySize, SMEM_BYTES);

    prep_fused_kernel<<<dim3(HH, NB, 2), 256>>>(x, wgt);

    dim3 grid(WW / TCOLS, HH / TROWS, NB);   // (7, 28, 2) = 392 CTAs
    conv3x3_i8_kernel<<<grid, 256, SMEM_BYTES>>>(bias, out);
}

// round 14
// speedup vs baseline: 1.1603x; 1.1603x over previous
#include <cuda_runtime.h>
#include <cstdint>

#define IN_C  64
#define OUT_C 64
#define HH    112
#define WW    112
#define NB    2

#define TROWS 4
#define TCOLS 16
#define KTOT  576
#define NTAP  9

// raw planes: [window 108][ic 64] int8, row stride 80 B
#define RAW_WIN 108
#define RAW_STRIDE 80

// smem offsets (main kernel)
#define OFF_RAW1 0u
#define OFF_RAW2 8640u
#define OFF_BIAS 17280u
#define SMEM_BYTES 17536u

// quantization scales
#define SX1 24.0f
#define SX2 6144.0f
#define SW1 512.0f
#define SW2 131072.0f
#define C1F (1.0f/12288.0f)
#define C2F (1.0f/3145728.0f)

// B in fragment order: [tap 9][wn 2][g 8][lane 32] uint4  (73728 B)
__device__ __align__(16) uint4 FB_g[NTAP * 2 * 8 * 32];
// pre-quantized x planes, NHWC: [b][y][x][ic]
__device__ __align__(16) int8_t xq1_g[NB * HH * WW * IN_C];
__device__ __align__(16) int8_t xq2_g[NB * HH * WW * IN_C];

__device__ __forceinline__ uint32_t smem_u32(const void* p) {
    uint32_t a;
    asm("{ .reg .u64 t; cvta.to.shared.u64 t, %1; cvt.u32.u64 %0, t; }" : "=r"(a) : "l"(p));
    return a;
}
__device__ __forceinline__ void mma_s8(int* d, const uint32_t* a, const uint32_t* b) {
    asm volatile(
        "mma.sync.aligned.m16n8k32.row.col.s32.s8.s8.s32 "
        "{%0,%1,%2,%3}, {%4,%5,%6,%7}, {%8,%9}, {%0,%1,%2,%3};"
        : "+r"(d[0]), "+r"(d[1]), "+r"(d[2]), "+r"(d[3])
        : "r"(a[0]), "r"(a[1]), "r"(a[2]), "r"(a[3]), "r"(b[0]), "r"(b[1]));
}
__device__ __forceinline__ void ldmx4(uint32_t* r, uint32_t addr) {
    asm volatile("ldmatrix.sync.aligned.m8n8.x4.shared.b16 {%0,%1,%2,%3}, [%4];"
        : "=r"(r[0]), "=r"(r[1]), "=r"(r[2]), "=r"(r[3]) : "r"(addr));
}
__device__ __forceinline__ int clampi(int v) { return max(-127, min(127, v)); }

// ---- fused pre-kernel ----
// grid (130, 2, 2), 256 threads.
//   y <  112          : x quantize+transpose (z = ic-half, r13 scheme)
//   y >= 112, b=0,z=0 : weight-fragment emission, blocks 0..17 (18*256 = 4608 uint4)
__global__ void __launch_bounds__(256)
prep_fused_kernel(const float* __restrict__ x, const float* __restrict__ wgt)
{
    __shared__ uint32_t s1w[WW * 9];
    __shared__ uint32_t s2w[WW * 9];

    const int tid = threadIdx.x;
    const int y   = blockIdx.x;
    const int b   = blockIdx.y;
    const int h   = blockIdx.z;

    if (y >= HH) {
        // ---- weight fragments ----
        if (b != 0 || h != 0) return;
        const int t = (y - HH) * 256 + tid;     // 0..4607
        if (t >= NTAP * 2 * 8 * 32) return;
        const int lane = t & 31;
        const int g    = (t >> 5) & 7;
        const int wnl  = (t >> 8) & 1;
        const int tap  = t >> 9;
        const int kslot = g >> 1;               // 0:B2 1:B3 2:Bk0 3:Bk1
        const int hh    = g & 1;
        const int ko    = ((kslot + 2) & 3) * 32;   // 64,96,0,32
        uint32_t wds[4];
        #pragma unroll
        for (int i = 0; i < 4; ++i) {
            const int n = wnl * 32 + hh * 16 + ((i >> 1) << 3) + (lane >> 2);
            uint32_t pk = 0;
            #pragma unroll
            for (int j = 0; j < 4; ++j) {
                const int kb = ko + ((i & 1) << 4) + ((lane & 3) << 2) + j;
                const int ic = kb & 63;
                const float w = wgt[n * KTOT + ic * 9 + tap];
                int w1 = clampi(__float2int_rn(w * SW1));
                const float rw = w - (float)w1 * (1.0f / SW1);
                int w2 = clampi(__float2int_rn(rw * SW2));
                const int val = (kb < 64) ? w2 : w1;
                pk |= (uint32_t)(uint8_t)(int8_t)val << (j * 8);
            }
            wds[i] = pk;
        }
        FB_g[t] = make_uint4(wds[0], wds[1], wds[2], wds[3]);
        return;
    }

    // ---- x quantize: 8 ic-groups x 112 x-positions ----
    for (int i = tid; i < 8 * WW; i += 256) {
        const int icl = i / WW;
        const int xx  = i - icl * WW;
        const int icg = h * 8 + icl;
        uint32_t p1 = 0, p2 = 0;
        #pragma unroll
        for (int j = 0; j < 4; ++j) {
            const float v = x[((b * IN_C + icg * 4 + j) * HH + y) * WW + xx];
            int x1 = clampi(__float2int_rn(v * SX1));
            const float rx = v - (float)x1 * (1.0f / SX1);
            int x2 = clampi(__float2int_rn(rx * SX2));
            p1 |= (uint32_t)(uint8_t)(int8_t)x1 << (j * 8);
            p2 |= (uint32_t)(uint8_t)(int8_t)x2 << (j * 8);
        }
        s1w[xx * 9 + icl] = p1;
        s2w[xx * 9 + icl] = p2;
    }
    __syncthreads();

    const int rowbase = ((b * HH + y) * WW) * IN_C;
    for (int i = tid; i < 448; i += 256) {
        const int pl = i >= 224;
        const int ii = pl ? i - 224 : i;
        const int xx = ii >> 1;
        const int ql = ii & 1;
        const int w0 = xx * 9 + ql * 4;
        const uint32_t* s = pl ? s2w : s1w;
        uint4 v = make_uint4(s[w0], s[w0 + 1], s[w0 + 2], s[w0 + 3]);
        int8_t* dst = pl ? xq2_g : xq1_g;
        *(uint4*)&dst[rowbase + xx * IN_C + (h * 2 + ql) * 16] = v;
    }
}

// ---- main kernel: 128 threads, 4 warps of 32m x 32n, NO barriers in tap loop ----
__global__ void __launch_bounds__(128, 4)
conv3x3_i8_kernel(const float* __restrict__ bias,
                  float* __restrict__ out)
{
    extern __shared__ char sm[];
    const uint32_t sb = smem_u32(sm);

    const int tid  = threadIdx.x;
    const int wid  = tid >> 5;
    const int lane = tid & 31;
    const int grp  = lane >> 2;
    const int tid4 = lane & 3;

    const int wm = wid & 1;         // 2 m-groups of 32
    const int wn = wid >> 1;        // 2 n-groups of 32

    const int col0 = blockIdx.x * TCOLS;
    const int row0 = blockIdx.y * TROWS;
    const int b    = blockIdx.z;

    float* biass = (float*)(sm + OFF_BIAS);

    // ---- stage raw planes: 16B copies from pre-quantized NHWC globals ----
    for (int e = tid; e < 432; e += 128) {
        const int wdw = e >> 2;
        const int icg = e & 3;
        const int r   = wdw / 18;
        const int c   = wdw - r * 18;
        const int gr  = row0 - 1 + r;
        const int gc  = col0 - 1 + c;
        uint4 v1 = make_uint4(0, 0, 0, 0), v2 = v1;
        if ((unsigned)gr < (unsigned)HH && (unsigned)gc < (unsigned)WW) {
            const int gi = (((b * HH + gr) * WW) + gc) * IN_C + icg * 16;
            v1 = *(const uint4*)&xq1_g[gi];
            v2 = *(const uint4*)&xq2_g[gi];
        }
        const uint32_t so = (uint32_t)wdw * RAW_STRIDE + (uint32_t)icg * 16u;
        *(uint4*)(sm + OFF_RAW1 + so) = v1;
        *(uint4*)(sm + OFF_RAW2 + so) = v2;
    }
    if (tid < OUT_C) biass[tid] = bias[tid];

    // accumulators
    int acc1[2][4][4], acc2[2][4][4];
    #pragma unroll
    for (int f = 0; f < 2; ++f)
        #pragma unroll
        for (int g = 0; g < 4; ++g)
            #pragma unroll
            for (int qq = 0; qq < 4; ++qq) { acc1[f][g][qq] = 0; acc2[f][g][qq] = 0; }

    // ---- per-lane A ldmatrix base addresses (direct from raw planes) ----
    const int q  = lane >> 3;
    const int rq = lane & 7;
    const int kq = q >> 1;
    const int m0 = wm * 32 + ((q & 1) << 3) + rq;
    const int m1 = m0 + 16;
    const uint32_t baseA0 = sb + (uint32_t)((m0 >> 4) * 18 + (m0 & 15)) * RAW_STRIDE + (uint32_t)(kq << 4);
    const uint32_t baseA1 = sb + (uint32_t)((m1 >> 4) * 18 + (m1 & 15)) * RAW_STRIDE + (uint32_t)(kq << 4);

    __syncthreads();                // raw planes staged; last barrier in the kernel

    // B fragment pointer for this warp-half and lane
    const uint4* fb = FB_g + wn * (8 * 32) + lane;

    #pragma unroll 1
    for (int tap = 0; tap < NTAP; ++tap) {
        const int dy = tap / 3, dx = tap - dy * 3;
        const uint32_t tOff = (uint32_t)(dy * 18 + dx) * RAW_STRIDE;
        const uint32_t aA0  = baseA0 + tOff;
        const uint32_t aA1  = baseA1 + tOff;
        const uint4* fbt = fb + tap * (2 * 8 * 32);

        // ---- B fragments: 8 coalesced LDG.128 straight into operand regs ----
        uint32_t Bw[32];
        #pragma unroll
        for (int g = 0; g < 8; ++g) {
            const uint4 v = fbt[g * 32];
            Bw[g * 4]     = v.x; Bw[g * 4 + 1] = v.y;
            Bw[g * 4 + 2] = v.z; Bw[g * 4 + 3] = v.w;
        }
        uint32_t* B2  = Bw;          // g0,g1: w1 ic 0-31  (regs 0-7)
        uint32_t* B3  = Bw + 8;      // g2,g3: w1 ic 32-63
        uint32_t* Bk0 = Bw + 16;     // g4,g5: w2 ic 0-31
        uint32_t* Bk1 = Bw + 24;     // g6,g7: w2 ic 32-63

        // ks = 2, 3: cross x2*w1 (A plane 2)
        #pragma unroll
        for (int ks = 2; ks < 4; ++ks) {
            uint32_t A0[4], A1[4];
            const uint32_t ko = OFF_RAW2 + (uint32_t)(ks & 1) * 32u;
            ldmx4(A0, aA0 + ko);
            ldmx4(A1, aA1 + ko);
            uint32_t* Bk = (ks == 2) ? B2 : B3;
            #pragma unroll
            for (int g = 0; g < 4; ++g) {
                mma_s8(acc2[0][g], A0, Bk + 2 * g);
                mma_s8(acc2[1][g], A1, Bk + 2 * g);
            }
        }
        // ks = 0, 1: cross x1*w2 into acc2, main x1*w1 into acc1
        #pragma unroll
        for (int ks = 0; ks < 2; ++ks) {
            uint32_t A0[4], A1[4];
            const uint32_t ko = OFF_RAW1 + (uint32_t)ks * 32u;
            ldmx4(A0, aA0 + ko);
            ldmx4(A1, aA1 + ko);
            uint32_t* Bc = (ks == 0) ? Bk0 : Bk1;
            uint32_t* Bm = (ks == 0) ? B2  : B3;
            #pragma unroll
            for (int g = 0; g < 4; ++g) {
                mma_s8(acc2[0][g], A0, Bc + 2 * g);
                mma_s8(acc2[1][g], A1, Bc + 2 * g);
                mma_s8(acc1[0][g], A0, Bm + 2 * g);
                mma_s8(acc1[1][g], A1, Bm + 2 * g);
            }
        }
    }

    // ---- epilogue: reconstruct fp32, add bias, store ----
    #pragma unroll
    for (int f = 0; f < 2; ++f) {
        #pragma unroll
        for (int half = 0; half < 2; ++half) {
            const int m  = wm * 32 + f * 16 + half * 8 + grp;
            const int gy = row0 + (m >> 4);
            const int gx = col0 + (m & 15);
            float* op = &out[((b * OUT_C) * HH + gy) * WW + gx];
            #pragma unroll
            for (int g = 0; g < 4; ++g) {
                const int n = wn * 32 + g * 8 + tid4 * 2;
                const float v0 = (float)acc1[f][g][half * 2]     * C1F
                               + (float)acc2[f][g][half * 2]     * C2F + biass[n];
                const float v1 = (float)acc1[f][g][half * 2 + 1] * C1F
                               + (float)acc2[f][g][half * 2 + 1] * C2F + biass[n + 1];
                op[n * (HH * WW)]       = v0;
                op[(n + 1) * (HH * WW)] = v1;
            }
        }
    }
}

extern "C" void kernel_launch(void* const* d_in, const int* in_sizes, int n_in,
                              void* d_out, int out_size)
{
    const float* x    = (const float*)d_in[0];
    const float* wgt  = (const float*)d_in[1];
    const float* bias = (const float*)d_in[2];
    float* out        = (float*)d_out;

    cudaFuncSetAttribute(conv3x3_i8_kernel,
                         cudaFuncAttributeMaxDynamicSharedMemorySize, SMEM_BYTES);

    prep_fused_kernel<<<dim3(HH + 18, NB, 2), 256>>>(x, wgt);

    dim3 grid(WW / TCOLS, HH / TROWS, NB);   // (7, 28, 2) = 392 CTAs
    conv3x3_i8_kernel<<<grid, 128, SMEM_BYTES>>>(bias, out);
}

// round 15
// speedup vs baseline: 1.2870x; 1.1093x over previous
#include <cuda_runtime.h>
#include <cstdint>

#define IN_C  64
#define OUT_C 64
#define HH    112
#define WW    112
#define NB    2

#define TROWS 4
#define TCOLS 16
#define KTOT  576
#define NTAP  9

// raw planes: [window 108][ic 64] int8, row stride 80 B
#define RAW_WIN 108
#define RAW_STRIDE 80

// smem offsets (main kernel)
#define OFF_RAW1 0u
#define OFF_RAW2 8640u
#define OFF_BIAS 17280u
#define SMEM_BYTES 17536u

// quantization scales
#define SX1 24.0f
#define SX2 6144.0f
#define SW1 512.0f
#define SW2 131072.0f
#define C1F (1.0f/12288.0f)
#define C2F (1.0f/3145728.0f)

// B in fragment order: [tap 9][wn 2][g 8][lane 32] uint4  (73728 B)
__device__ __align__(16) uint4 FB_g[NTAP * 2 * 8 * 32];
// pre-quantized x planes, NHWC: [b][y][x][ic]
__device__ __align__(16) int8_t xq1_g[NB * HH * WW * IN_C];
__device__ __align__(16) int8_t xq2_g[NB * HH * WW * IN_C];

__device__ __forceinline__ uint32_t smem_u32(const void* p) {
    uint32_t a;
    asm("{ .reg .u64 t; cvta.to.shared.u64 t, %1; cvt.u32.u64 %0, t; }" : "=r"(a) : "l"(p));
    return a;
}
__device__ __forceinline__ void mma_s8(int* d, const uint32_t* a, const uint32_t* b) {
    asm volatile(
        "mma.sync.aligned.m16n8k32.row.col.s32.s8.s8.s32 "
        "{%0,%1,%2,%3}, {%4,%5,%6,%7}, {%8,%9}, {%0,%1,%2,%3};"
        : "+r"(d[0]), "+r"(d[1]), "+r"(d[2]), "+r"(d[3])
        : "r"(a[0]), "r"(a[1]), "r"(a[2]), "r"(a[3]), "r"(b[0]), "r"(b[1]));
}
__device__ __forceinline__ void ldmx4(uint32_t* r, uint32_t addr) {
    asm volatile("ldmatrix.sync.aligned.m8n8.x4.shared.b16 {%0,%1,%2,%3}, [%4];"
        : "=r"(r[0]), "=r"(r[1]), "=r"(r[2]), "=r"(r[3]) : "r"(addr));
}
__device__ __forceinline__ int clampi(int v) { return max(-127, min(127, v)); }

// ---- fused pre-kernel ----
// grid (130, 2, 2), 256 threads.
//   y <  112 : x quantize+transpose (z = ic-half)
//   y >= 112 : weight-fragment emission, 72 blocks x 256 = 18432 uint32 outputs
__global__ void __launch_bounds__(256)
prep_fused_kernel(const float* __restrict__ x, const float* __restrict__ wgt)
{
    __shared__ uint32_t s1w[WW * 9];
    __shared__ uint32_t s2w[WW * 9];

    const int tid = threadIdx.x;
    const int y   = blockIdx.x;
    const int b   = blockIdx.y;
    const int h   = blockIdx.z;

    if (y >= HH) {
        // one uint32 fragment word per thread: 4 LDG + coalesced STG.32
        const int flat2 = (y - HH) * (NB * 2) + b * 2 + h;   // 0..71
        const int t2 = flat2 * 256 + tid;                    // 0..18431
        const int i    = t2 & 3;
        const int lane = (t2 >> 2) & 31;
        const int g    = (t2 >> 7) & 7;
        const int wnl  = (t2 >> 10) & 1;
        const int tap  = t2 >> 11;                            // 0..8
        const int kslot = g >> 1;               // 0:B2 1:B3 2:Bk0 3:Bk1
        const int hh    = g & 1;
        const int ko    = ((kslot + 2) & 3) * 32;   // 64,96,0,32
        const int n = wnl * 32 + hh * 16 + ((i >> 1) << 3) + (lane >> 2);
        uint32_t pk = 0;
        #pragma unroll
        for (int j = 0; j < 4; ++j) {
            const int kb = ko + ((i & 1) << 4) + ((lane & 3) << 2) + j;
            const int ic = kb & 63;
            const float w = wgt[n * KTOT + ic * 9 + tap];
            int w1 = clampi(__float2int_rn(w * SW1));
            const float rw = w - (float)w1 * (1.0f / SW1);
            int w2 = clampi(__float2int_rn(rw * SW2));
            const int val = (kb < 64) ? w2 : w1;
            pk |= (uint32_t)(uint8_t)(int8_t)val << (j * 8);
        }
        ((uint32_t*)FB_g)[t2] = pk;
        return;
    }

    // ---- x quantize: 8 ic-groups x 112 x-positions ----
    for (int i = tid; i < 8 * WW; i += 256) {
        const int icl = i / WW;
        const int xx  = i - icl * WW;
        const int icg = h * 8 + icl;
        uint32_t p1 = 0, p2 = 0;
        #pragma unroll
        for (int j = 0; j < 4; ++j) {
            const float v = x[((b * IN_C + icg * 4 + j) * HH + y) * WW + xx];
            int x1 = clampi(__float2int_rn(v * SX1));
            const float rx = v - (float)x1 * (1.0f / SX1);
            int x2 = clampi(__float2int_rn(rx * SX2));
            p1 |= (uint32_t)(uint8_t)(int8_t)x1 << (j * 8);
            p2 |= (uint32_t)(uint8_t)(int8_t)x2 << (j * 8);
        }
        s1w[xx * 9 + icl] = p1;
        s2w[xx * 9 + icl] = p2;
    }
    __syncthreads();

    const int rowbase = ((b * HH + y) * WW) * IN_C;
    for (int i = tid; i < 448; i += 256) {
        const int pl = i >= 224;
        const int ii = pl ? i - 224 : i;
        const int xx = ii >> 1;
        const int ql = ii & 1;
        const int w0 = xx * 9 + ql * 4;
        const uint32_t* s = pl ? s2w : s1w;
        uint4 v = make_uint4(s[w0], s[w0 + 1], s[w0 + 2], s[w0 + 3]);
        int8_t* dst = pl ? xq2_g : xq1_g;
        *(uint4*)&dst[rowbase + xx * IN_C + (h * 2 + ql) * 16] = v;
    }
}

// ---- main kernel: 128 threads, 4 warps of 32m x 32n ----
// Barrier-free, fully-unrolled tap loop with register-double-buffered B.
__global__ void __launch_bounds__(128, 3)
conv3x3_i8_kernel(const float* __restrict__ bias,
                  float* __restrict__ out)
{
    extern __shared__ char sm[];
    const uint32_t sb = smem_u32(sm);

    const int tid  = threadIdx.x;
    const int wid  = tid >> 5;
    const int lane = tid & 31;
    const int grp  = lane >> 2;
    const int tid4 = lane & 3;

    const int wm = wid & 1;         // 2 m-groups of 32
    const int wn = wid >> 1;        // 2 n-groups of 32

    const int col0 = blockIdx.x * TCOLS;
    const int row0 = blockIdx.y * TROWS;
    const int b    = blockIdx.z;

    float* biass = (float*)(sm + OFF_BIAS);

    // ---- stage raw planes: 16B copies from pre-quantized NHWC globals ----
    for (int e = tid; e < 432; e += 128) {
        const int wdw = e >> 2;
        const int icg = e & 3;
        const int r   = wdw / 18;
        const int c   = wdw - r * 18;
        const int gr  = row0 - 1 + r;
        const int gc  = col0 - 1 + c;
        uint4 v1 = make_uint4(0, 0, 0, 0), v2 = v1;
        if ((unsigned)gr < (unsigned)HH && (unsigned)gc < (unsigned)WW) {
            const int gi = (((b * HH + gr) * WW) + gc) * IN_C + icg * 16;
            v1 = *(const uint4*)&xq1_g[gi];
            v2 = *(const uint4*)&xq2_g[gi];
        }
        const uint32_t so = (uint32_t)wdw * RAW_STRIDE + (uint32_t)icg * 16u;
        *(uint4*)(sm + OFF_RAW1 + so) = v1;
        *(uint4*)(sm + OFF_RAW2 + so) = v2;
    }
    if (tid < OUT_C) biass[tid] = bias[tid];

    // accumulators
    int acc1[2][4][4], acc2[2][4][4];
    #pragma unroll
    for (int f = 0; f < 2; ++f)
        #pragma unroll
        for (int g = 0; g < 4; ++g)
            #pragma unroll
            for (int qq = 0; qq < 4; ++qq) { acc1[f][g][qq] = 0; acc2[f][g][qq] = 0; }

    // ---- per-lane A ldmatrix base addresses ----
    const int q  = lane >> 3;
    const int rq = lane & 7;
    const int kq = q >> 1;
    const int m0 = wm * 32 + ((q & 1) << 3) + rq;
    const int m1 = m0 + 16;
    const uint32_t baseA0 = sb + (uint32_t)((m0 >> 4) * 18 + (m0 & 15)) * RAW_STRIDE + (uint32_t)(kq << 4);
    const uint32_t baseA1 = sb + (uint32_t)((m1 >> 4) * 18 + (m1 & 15)) * RAW_STRIDE + (uint32_t)(kq << 4);

    const uint4* fb = FB_g + wn * (8 * 32) + lane;

    // B double buffer in registers
    uint32_t Bw[2][32];
    #pragma unroll
    for (int g = 0; g < 8; ++g) {
        const uint4 v = fb[g * 32];
        Bw[0][g * 4]     = v.x; Bw[0][g * 4 + 1] = v.y;
        Bw[0][g * 4 + 2] = v.z; Bw[0][g * 4 + 3] = v.w;
    }

    __syncthreads();                // raw planes staged; last barrier

    #pragma unroll
    for (int tap = 0; tap < NTAP; ++tap) {
        const int cur = tap & 1, nxt = cur ^ 1;

        // prefetch next tap's B fragments FIRST (hidden under this tap's MMAs)
        if (tap < NTAP - 1) {
            const uint4* fbt = fb + (tap + 1) * (2 * 8 * 32);
            #pragma unroll
            for (int g = 0; g < 8; ++g) {
                const uint4 v = fbt[g * 32];
                Bw[nxt][g * 4]     = v.x; Bw[nxt][g * 4 + 1] = v.y;
                Bw[nxt][g * 4 + 2] = v.z; Bw[nxt][g * 4 + 3] = v.w;
            }
        }

        const int dy = tap / 3, dx = tap - dy * 3;
        const uint32_t tOff = (uint32_t)(dy * 18 + dx) * RAW_STRIDE;
        const uint32_t aA0  = baseA0 + tOff;
        const uint32_t aA1  = baseA1 + tOff;

        uint32_t* B2  = Bw[cur];          // w1 ic 0-31
        uint32_t* B3  = Bw[cur] + 8;      // w1 ic 32-63
        uint32_t* Bk0 = Bw[cur] + 16;     // w2 ic 0-31
        uint32_t* Bk1 = Bw[cur] + 24;     // w2 ic 32-63

        // ks = 2, 3: cross x2*w1 (A plane 2)
        #pragma unroll
        for (int ks = 2; ks < 4; ++ks) {
            uint32_t A0[4], A1[4];
            const uint32_t ko = OFF_RAW2 + (uint32_t)(ks & 1) * 32u;
            ldmx4(A0, aA0 + ko);
            ldmx4(A1, aA1 + ko);
            uint32_t* Bk = (ks == 2) ? B2 : B3;
            #pragma unroll
            for (int g = 0; g < 4; ++g) {
                mma_s8(acc2[0][g], A0, Bk + 2 * g);
                mma_s8(acc2[1][g], A1, Bk + 2 * g);
            }
        }
        // ks = 0, 1: cross x1*w2 into acc2, main x1*w1 into acc1
        #pragma unroll
        for (int ks = 0; ks < 2; ++ks) {
            uint32_t A0[4], A1[4];
            const uint32_t ko = OFF_RAW1 + (uint32_t)ks * 32u;
            ldmx4(A0, aA0 + ko);
            ldmx4(A1, aA1 + ko);
            uint32_t* Bc = (ks == 0) ? Bk0 : Bk1;
            uint32_t* Bm = (ks == 0) ? B2  : B3;
            #pragma unroll
            for (int g = 0; g < 4; ++g) {
                mma_s8(acc2[0][g], A0, Bc + 2 * g);
                mma_s8(acc2[1][g], A1, Bc + 2 * g);
                mma_s8(acc1[0][g], A0, Bm + 2 * g);
                mma_s8(acc1[1][g], A1, Bm + 2 * g);
            }
        }
    }

    // ---- epilogue: reconstruct fp32, add bias, store ----
    #pragma unroll
    for (int f = 0; f < 2; ++f) {
        #pragma unroll
        for (int half = 0; half < 2; ++half) {
            const int m  = wm * 32 + f * 16 + half * 8 + grp;
            const int gy = row0 + (m >> 4);
            const int gx = col0 + (m & 15);
            float* op = &out[((b * OUT_C) * HH + gy) * WW + gx];
            #pragma unroll
            for (int g = 0; g < 4; ++g) {
                const int n = wn * 32 + g * 8 + tid4 * 2;
                const float v0 = (float)acc1[f][g][half * 2]     * C1F
                               + (float)acc2[f][g][half * 2]     * C2F + biass[n];
                const float v1 = (float)acc1[f][g][half * 2 + 1] * C1F
                               + (float)acc2[f][g][half * 2 + 1] * C2F + biass[n + 1];
                op[n * (HH * WW)]       = v0;
                op[(n + 1) * (HH * WW)] = v1;
            }
        }
    }
}

extern "C" void kernel_launch(void* const* d_in, const int* in_sizes, int n_in,
                              void* d_out, int out_size)
{
    const float* x    = (const float*)d_in[0];
    const float* wgt  = (const float*)d_in[1];
    const float* bias = (const float*)d_in[2];
    float* out        = (float*)d_out;

    cudaFuncSetAttribute(conv3x3_i8_kernel,
                         cudaFuncAttributeMaxDynamicSharedMemorySize, SMEM_BYTES);

    prep_fused_kernel<<<dim3(HH + 18, NB, 2), 256>>>(x, wgt);

    dim3 grid(WW / TCOLS, HH / TROWS, NB);   // (7, 28, 2) = 392 CTAs
    conv3x3_i8_kernel<<<grid, 128, SMEM_BYTES>>>(bias, out);
}